// round 13
// baseline (speedup 1.0000x reference)
#include <cuda_runtime.h>
#include <cstdint>

#define T_STEPS 8192
#define H_DIM 256
#define E_DIM 256
#define G_DIM 1024   // 4*H
#define CL 16        // cluster size (nonportable on sm_103)
#define EPC 16       // h elements per CTA
#define THREADS 512  // 16 warps

// 32 MB scratch for xg = emb@W_ih^T + bias  (allocation-free rule: device global)
__device__ float g_xg[(size_t)T_STEPS * G_DIM];

// ---------------------------------------------------------------------------
// helpers
// ---------------------------------------------------------------------------
__device__ __forceinline__ uint32_t smem_u32(const void* p) {
    uint32_t a;
    asm("{ .reg .u64 t; cvta.to.shared.u64 t, %1; cvt.u32.u64 %0, t; }"
        : "=r"(a) : "l"(p));
    return a;
}

__device__ __forceinline__ void ffma2(unsigned long long& d,
                                      unsigned long long a,
                                      unsigned long long b) {
    asm("fma.rn.f32x2 %0, %1, %2, %0;" : "+l"(d) : "l"(a), "l"(b));
}
__device__ __forceinline__ void fadd2(unsigned long long& d,
                                      unsigned long long a) {
    asm("add.rn.f32x2 %0, %0, %1;" : "+l"(d) : "l"(a));
}

__device__ __forceinline__ float lo32(unsigned long long v) {
    return __uint_as_float((uint32_t)v);
}
__device__ __forceinline__ float hi32(unsigned long long v) {
    return __uint_as_float((uint32_t)(v >> 32));
}

__device__ __forceinline__ float tanh_fast(float x) {
    float r;
    asm("tanh.approx.f32 %0, %1;" : "=f"(r) : "f"(x));
    return r;
}
// sigmoid(x) = 0.5*tanh(0.5x) + 0.5   (MUFU tanh, no div)
__device__ __forceinline__ float sigmoid_fast(float x) {
    return fmaf(0.5f, tanh_fast(0.5f * x), 0.5f);
}

__device__ __forceinline__ void mbar_wait(uint32_t addr, uint32_t parity) {
    uint32_t done;
    asm volatile(
        "{\n\t.reg .pred p;\n\t"
        "mbarrier.try_wait.parity.acquire.cta.shared::cta.b64 p, [%1], %2;\n\t"
        "selp.b32 %0, 1, 0, p;\n\t}"
        : "=r"(done) : "r"(addr), "r"(parity) : "memory");
    if (!done) {
        asm volatile(
            "{\n\t.reg .pred P1;\n"
            "WL_%=:\n\t"
            "mbarrier.try_wait.parity.acquire.cta.shared::cta.b64 P1, [%0], %1, 0x989680;\n\t"
            "@P1 bra.uni WD_%=;\n\t"
            "bra.uni WL_%=;\n"
            "WD_%=:\n\t}"
            :: "r"(addr), "r"(parity) : "memory");
    }
}

// ---------------------------------------------------------------------------
// Kernel A: xg[t][r] = sum_k emb[tokens[t]][k] * W_ih[r][k] + (b_ih[r]+b_hh[r])
// ---------------------------------------------------------------------------
__global__ __launch_bounds__(256) void xg_gemm(const int* __restrict__ tokens,
                                               const float* __restrict__ emb,
                                               const float* __restrict__ Wih,
                                               const float* __restrict__ bih,
                                               const float* __restrict__ bhh) {
    __shared__ __align__(16) float As[32][132];
    __shared__ __align__(16) float Bs[32][132];
    __shared__ int stok[128];

    const int tid = threadIdx.x;
    const int t0 = blockIdx.y * 128;
    const int r0 = blockIdx.x * 128;

    if (tid < 128) stok[tid] = tokens[t0 + tid];
    __syncthreads();

    const int ty = tid >> 4;
    const int tx = tid & 15;

    float acc[8][8];
#pragma unroll
    for (int i = 0; i < 8; i++)
#pragma unroll
        for (int j = 0; j < 8; j++) acc[i][j] = 0.0f;

    for (int k0 = 0; k0 < E_DIM; k0 += 32) {
#pragma unroll
        for (int q = 0; q < 4; q++) {
            int v = q * 256 + tid;
            int row = v >> 3;
            int c4 = v & 7;
            float4 a = *(const float4*)(emb + (size_t)stok[row] * E_DIM + k0 + c4 * 4);
            As[c4 * 4 + 0][row] = a.x; As[c4 * 4 + 1][row] = a.y;
            As[c4 * 4 + 2][row] = a.z; As[c4 * 4 + 3][row] = a.w;
            float4 b = *(const float4*)(Wih + (size_t)(r0 + row) * E_DIM + k0 + c4 * 4);
            Bs[c4 * 4 + 0][row] = b.x; Bs[c4 * 4 + 1][row] = b.y;
            Bs[c4 * 4 + 2][row] = b.z; Bs[c4 * 4 + 3][row] = b.w;
        }
        __syncthreads();

#pragma unroll
        for (int k = 0; k < 32; k++) {
            float a[8], b[8];
            float4 a0 = *(const float4*)&As[k][ty * 8];
            float4 a1 = *(const float4*)&As[k][ty * 8 + 4];
            float4 b0 = *(const float4*)&Bs[k][tx * 8];
            float4 b1 = *(const float4*)&Bs[k][tx * 8 + 4];
            a[0]=a0.x; a[1]=a0.y; a[2]=a0.z; a[3]=a0.w;
            a[4]=a1.x; a[5]=a1.y; a[6]=a1.z; a[7]=a1.w;
            b[0]=b0.x; b[1]=b0.y; b[2]=b0.z; b[3]=b0.w;
            b[4]=b1.x; b[5]=b1.y; b[6]=b1.z; b[7]=b1.w;
#pragma unroll
            for (int i = 0; i < 8; i++)
#pragma unroll
                for (int j = 0; j < 8; j++)
                    acc[i][j] = fmaf(a[i], b[j], acc[i][j]);
        }
        __syncthreads();
    }

#pragma unroll
    for (int j = 0; j < 8; j++) {
        int r = r0 + tx * 8 + j;
        float bias = bih[r] + bhh[r];
#pragma unroll
        for (int i = 0; i < 8; i++) {
            g_xg[(size_t)(t0 + ty * 8 + i) * G_DIM + r] = acc[i][j] + bias;
        }
    }
}

// ---------------------------------------------------------------------------
// Kernel B: persistent 16-CTA cluster LSTM scan — st.async, per-source bars.
//   CTA owns 16 elements (E = 16*rank + e). 16 warps.
//   Phase 1: warp w covers K-slice [16w,16w+16) (= source CTA w's elements,
//     so warp w waits ONLY bars[w][t&1]). Lane l: elem e=l&15, gate pair
//     g0=2*(l>>4). 16 ffma2/lane. STS u64 partial into part[t&1][w][e][g0].
//   Phase 2 (after __syncthreads, warp 0): all 32 lanes reduce 16 partials
//     (lane l: elem l&15, gates g0=2*(l>>4)); 64-bit shfl-xor-16 swaps the
//     (g,o) sums to lanes 0-15, which run MUFU activations (c in-lane).
//     Push: every lane sends 2 st.async.v4.b32 packets (lane l: packets
//     2*(l>>4), +1; dest l&15), completing on dest bars[rank][(t+1)&1]
//     (expect_tx = 64B = 4 packets per source).
//   Safety: identical protocol shape to R9/R12 — per-source wait matches
//   per-source read; arm (by warp-w lane 0, at wait time) precedes our
//   phase-2 push of h(t+1) via __syncthreads; any source's t+2 sends are
//   gated on receiving our h(t+1).
// ---------------------------------------------------------------------------
__global__ __launch_bounds__(THREADS, 1)
void lstm_scan(const float* __restrict__ Whh, float* __restrict__ out) {
    __shared__ __align__(16) float hbuf[2][H_DIM];
    __shared__ __align__(16) float part[2][CL][EPC][4];
    __shared__ __align__(8) unsigned long long bars[CL][2];

    const uint32_t smem_h = smem_u32(&hbuf[0][0]);
    const uint32_t smem_bars = smem_u32(&bars[0][0]);

    const int tid = threadIdx.x;
    const int w = tid >> 5;        // warp = K-slice = source CTA index
    const int l = tid & 31;
    const int e = l & 15;          // element within CTA's 16
    const int g0 = 2 * (l >> 4);   // gate pair: 0 -> (i,f), 2 -> (g,o)
    uint32_t rank;
    asm("mov.u32 %0, %%cluster_ctarank;" : "=r"(rank));

    const int E = (int)rank * EPC + e;   // global h element

    // weights: 2 gate rows (g0, g0+1) of element E, K slice [16w,16w+16).
    unsigned long long wt[2][8];
#pragma unroll
    for (int g = 0; g < 2; g++) {
        const unsigned long long* wr = (const unsigned long long*)
            (Whh + (size_t)((g0 + g) * H_DIM + E) * H_DIM + 16 * w);
#pragma unroll
        for (int i = 0; i < 8; i++) wt[g][i] = wr[i];
    }

    // init
    for (int i = tid; i < 2 * H_DIM; i += THREADS) ((float*)hbuf)[i] = 0.0f;
    if (tid < 2 * CL) {
        asm volatile("mbarrier.init.shared.b64 [%0], %1;"
                     :: "r"(smem_bars + (uint32_t)tid * 8), "r"(1) : "memory");
    }
    __syncthreads();
    // pre-arm bars[w][1] for t=1 (one arm per source barrier)
    if (l == 0) {
        asm volatile("mbarrier.arrive.expect_tx.shared.b64 _, [%0], %1;"
                     :: "r"(smem_bars + (uint32_t)(w * 2 + 1) * 8), "r"(64)
                     : "memory");
    }
    __syncthreads();
    asm volatile("barrier.cluster.arrive.aligned;" ::: "memory");
    asm volatile("barrier.cluster.wait.aligned;" ::: "memory");

    // push lanes (warp 0, all 32): lane l sends packets pa=2*(l>>4), pa+1
    // (elems 4pa..4pa+3, 4pa+4..4pa+7) to dest CTA (l&15).
    uint32_t dsth = 0, dstb = 0;
    const int pa = 2 * (l >> 4);
    if (w == 0) {
        uint32_t hoff = smem_h + (uint32_t)(rank * EPC + 4 * pa) * 4;
        uint32_t boff = smem_bars + rank * 16;   // bars[rank][0]
        asm("mapa.shared::cluster.u32 %0, %1, %2;"
            : "=r"(dsth) : "r"(hoff), "r"(e));
        asm("mapa.shared::cluster.u32 %0, %1, %2;"
            : "=r"(dstb) : "r"(boff), "r"(e));
    }

    float c = 0.0f;
    float xn0 = 0.f, xn1 = 0.f, xn2 = 0.f, xn3 = 0.f;
    if (w == 0 && l < EPC) {
        xn0 = g_xg[0 * H_DIM + E];
        xn1 = g_xg[1 * H_DIM + E];
        xn2 = g_xg[2 * H_DIM + E];
        xn3 = g_xg[3 * H_DIM + E];
    }

    const uint32_t mybar0 = smem_bars + (uint32_t)(w * 2) * 8;
    const uint32_t mybar1 = mybar0 + 8;

    for (int t = 0; t < T_STEPS; t++) {
        const uint32_t mybar = (t & 1) ? mybar1 : mybar0;
        // ---- wait ONLY this warp's source CTA, then re-arm for t+2 ----
        if (t > 0) mbar_wait(mybar, (uint32_t)(((t - 1) >> 1) & 1));
        if (l == 0) {
            asm volatile("mbarrier.arrive.expect_tx.shared.b64 _, [%0], %1;"
                         :: "r"(mybar), "r"(64) : "memory");
        }

        // ---- phase 1: 2-gate partial dots over slice [16w,16w+16) ----
        const ulonglong2* hp =
            (const ulonglong2*)((const char*)hbuf + (t & 1) * (H_DIM * 4) + w * 64);
        unsigned long long hh[8];
#pragma unroll
        for (int i = 0; i < 4; i++) {
            ulonglong2 q = hp[i];
            hh[2 * i + 0] = q.x;
            hh[2 * i + 1] = q.y;
        }
        unsigned long long a0 = 0ull, a1 = 0ull;
#pragma unroll
        for (int j = 0; j < 8; j++) {
            ffma2(a0, wt[0][j], hh[j]);
            ffma2(a1, wt[1][j], hh[j]);
        }
        unsigned long long p2;
        {
            uint32_t plo = __float_as_uint(lo32(a0) + hi32(a0));
            uint32_t phi = __float_as_uint(lo32(a1) + hi32(a1));
            asm("mov.b64 %0, {%1, %2};" : "=l"(p2) : "r"(plo), "r"(phi));
        }
        *(unsigned long long*)&part[t & 1][w][e][g0] = p2;
        __syncthreads();

        // ---- phase 2: warp 0 reduces + MUFU activations + v4 push ----
        if (w == 0) {
            // lane l reduces gates (g0, g0+1) of elem e over 16 sources
            unsigned long long sS = 0ull;
#pragma unroll
            for (int ww = 0; ww < CL; ww++) {
                fadd2(sS, *(const unsigned long long*)&part[t & 1][ww][e][g0]);
            }
            // lanes 16-31 hold (g,o); swap to lanes 0-15
            unsigned long long sO = __shfl_xor_sync(0xFFFFFFFFu, sS, 16);

            float hv = 0.0f;
            if (l < EPC) {
                float iv = sigmoid_fast(lo32(sS) + xn0);
                float fv = sigmoid_fast(hi32(sS) + xn1);
                float gv = tanh_fast(lo32(sO) + xn2);
                float ov = sigmoid_fast(hi32(sO) + xn3);
                c = fv * c + iv * gv;
                hv = ov * tanh_fast(c);
            }

            if (t < T_STEPS - 1) {
                // gather packet elems via shfl; 2 v4 packets per lane
                const uint32_t hvu = __float_as_uint(hv);
                uint32_t q0 = __shfl_sync(0xFFFFFFFFu, hvu, 4 * pa + 0);
                uint32_t q1 = __shfl_sync(0xFFFFFFFFu, hvu, 4 * pa + 1);
                uint32_t q2 = __shfl_sync(0xFFFFFFFFu, hvu, 4 * pa + 2);
                uint32_t q3 = __shfl_sync(0xFFFFFFFFu, hvu, 4 * pa + 3);
                uint32_t r0 = __shfl_sync(0xFFFFFFFFu, hvu, 4 * pa + 4);
                uint32_t r1 = __shfl_sync(0xFFFFFFFFu, hvu, 4 * pa + 5);
                uint32_t r2 = __shfl_sync(0xFFFFFFFFu, hvu, 4 * pa + 6);
                uint32_t r3 = __shfl_sync(0xFFFFFFFFu, hvu, 4 * pa + 7);
                const uint32_t hoff = (uint32_t)((t + 1) & 1) * (H_DIM * 4);
                const uint32_t boff = (uint32_t)((t + 1) & 1) * 8;
                asm volatile(
                    "st.async.shared::cluster.mbarrier::complete_tx::bytes.v4.b32 "
                    "[%0], {%1,%2,%3,%4}, [%5];"
                    :: "r"(dsth + hoff), "r"(q0), "r"(q1), "r"(q2), "r"(q3),
                       "r"(dstb + boff)
                    : "memory");
                asm volatile(
                    "st.async.shared::cluster.mbarrier::complete_tx::bytes.v4.b32 "
                    "[%0], {%1,%2,%3,%4}, [%5];"
                    :: "r"(dsth + hoff + 16), "r"(r0), "r"(r1), "r"(r2), "r"(r3),
                       "r"(dstb + boff)
                    : "memory");
            }

            // off critical path: output + next xg prefetch
            if (l < EPC) {
                out[(size_t)t * H_DIM + E] = hv;
                if (t == T_STEPS - 1) {
                    out[(size_t)T_STEPS * H_DIM + E] = hv;
                    out[(size_t)T_STEPS * H_DIM + H_DIM + E] = c;
                }
                int tn = (t + 1 < T_STEPS) ? (t + 1) : t;
                const float* xr = g_xg + (size_t)tn * G_DIM + E;
                xn0 = xr[0]; xn1 = xr[256]; xn2 = xr[512]; xn3 = xr[768];
            }
        }
    }
}

// ---------------------------------------------------------------------------
extern "C" void kernel_launch(void* const* d_in, const int* in_sizes, int n_in,
                              void* d_out, int out_size) {
    const int* tokens = (const int*)d_in[0];
    const float* emb = (const float*)d_in[1];
    const float* Wih = (const float*)d_in[2];
    const float* Whh = (const float*)d_in[3];
    const float* bih = (const float*)d_in[4];
    const float* bhh = (const float*)d_in[5];
    float* out = (float*)d_out;

    dim3 gA(8, 64);
    xg_gemm<<<gA, 256>>>(tokens, emb, Wih, bih, bhh);

    // 16-CTA cluster (nonportable size on sm_103)
    cudaFuncSetAttribute(lstm_scan,
                         cudaFuncAttributeNonPortableClusterSizeAllowed, 1);
    cudaLaunchConfig_t cfg = {};
    cfg.gridDim = dim3(CL, 1, 1);
    cfg.blockDim = dim3(THREADS, 1, 1);
    cfg.dynamicSmemBytes = 0;
    cfg.stream = 0;
    cudaLaunchAttribute attrs[1];
    attrs[0].id = cudaLaunchAttributeClusterDimension;
    attrs[0].val.clusterDim.x = CL;
    attrs[0].val.clusterDim.y = 1;
    attrs[0].val.clusterDim.z = 1;
    cfg.attrs = attrs;
    cfg.numAttrs = 1;
    cudaLaunchKernelEx(&cfg, lstm_scan, Whh, out);
}